// round 7
// baseline (speedup 1.0000x reference)
#include <cuda_runtime.h>
#include <cuda_bf16.h>
#include <cstdint>

#define DEVINL __device__ __forceinline__

// ---------------- problem constants ----------------
constexpr int F  = 128;      // feature dim (K)
constexpr int B  = 256;      // batch
constexpr int R  = 512;      // J*B GEMM rows
constexpr int Q  = 65536;    // queue size
constexpr int TN = 64;       // queue rows per chunk
constexpr int QG = Q / TN;   // 1024 chunks
constexpr int SLOTS = 148;   // persistent CTAs (1 per SM)
constexpr int SSTR = 144;    // padded fp8 row stride in smem bytes (128 data + 16 pad)
constexpr float INV_T = 10.0f;
constexpr float LOG2E = 1.4426950408889634f;
constexpr float CEXP  = INV_T * LOG2E;   // exp(10*d) = 2^(CEXP*d); folded into A

// ---------------- scratch (no allocs allowed) ----------------
__device__ float g_sq[R * SLOTS];        // [row][slot] partials
__device__ float g_pos[R];
__device__ float g_sqrow[R];

// ---------------- helpers ----------------
DEVINL float ex2f(float x) { float y; asm("ex2.approx.ftz.f32 %0, %1;" : "=f"(y) : "f"(x)); return y; }

// pack 4 fp32 -> 4 e4m3 bytes (byte0 = f0)
DEVINL uint32_t pack_e4m3x4(float f0, float f1, float f2, float f3) {
    uint16_t lo, hi;
    asm("cvt.rn.satfinite.e4m3x2.f32 %0, %1, %2;" : "=h"(lo) : "f"(f1), "f"(f0));
    asm("cvt.rn.satfinite.e4m3x2.f32 %0, %1, %2;" : "=h"(hi) : "f"(f3), "f"(f2));
    return (uint32_t)lo | ((uint32_t)hi << 16);
}

DEVINL uint32_t smem_u32(const void* p) {
    uint32_t a;
    asm("{ .reg .u64 t; cvta.to.shared.u64 t, %1; cvt.u32.u64 %0, t; }" : "=r"(a) : "l"(p));
    return a;
}

// mma.sync m16n8k32 row.col e4m3 -> f32 accumulate (QMMA)
DEVINL void mma_fp8(float* d, const uint32_t* a, uint32_t b0, uint32_t b1) {
    asm volatile(
        "mma.sync.aligned.m16n8k32.row.col.f32.e4m3.e4m3.f32 "
        "{%0,%1,%2,%3}, {%4,%5,%6,%7}, {%8,%9}, {%0,%1,%2,%3};"
        : "+f"(d[0]), "+f"(d[1]), "+f"(d[2]), "+f"(d[3])
        : "r"(a[0]), "r"(a[1]), "r"(a[2]), "r"(a[3]), "r"(b0), "r"(b1));
}

DEVINL void ldsm_x4(uint32_t* r, uint32_t addr) {
    asm volatile("ldmatrix.sync.aligned.m8n8.x4.shared.b16 {%0,%1,%2,%3}, [%4];"
                 : "=r"(r[0]), "=r"(r[1]), "=r"(r[2]), "=r"(r[3]) : "r"(addr));
}

// ================= kernel 1: persistent FP8 MMA GEMM, fused cvt + exp row-sum =================
// grid = SLOTS. CTA slot: all 512 rows x chunks qg = slot, slot+SLOTS, ...
__global__ void __launch_bounds__(512, 1)
gemm_exp_kernel(const float* __restrict__ V, const float* __restrict__ queue) {
    // fp8 queue tile, double buffered: 64 rows x 144B
    __shared__ alignas(16) uint8_t tile[2][TN][SSTR];
    const uint32_t tb = smem_u32(&tile[0][0][0]);

    const int tid  = threadIdx.x;                // 0..511
    const int w    = tid >> 5;                   // 0..15 -> rows w*32..+31
    const int lane = tid & 31;
    const int g    = lane >> 2;
    const int tg   = lane & 3;
    const int slot = blockIdx.x;                 // 0..147

    // gmem chunk load: thread owns 16 consecutive floats (4 float4)
    float4 q4[4];
    auto ld_chunk = [&](int qg) {
        const float4* p = (const float4*)queue + (size_t)qg * (TN * F / 4) + tid * 4;
#pragma unroll
        for (int j = 0; j < 4; j++) q4[j] = p[j];
    };
    // convert + store 16 fp8 bytes into padded tile
    auto store_chunk = [&](int buf) {
        uint4 o;
        o.x = pack_e4m3x4(q4[0].x, q4[0].y, q4[0].z, q4[0].w);
        o.y = pack_e4m3x4(q4[1].x, q4[1].y, q4[1].z, q4[1].w);
        o.z = pack_e4m3x4(q4[2].x, q4[2].y, q4[2].z, q4[2].w);
        o.w = pack_e4m3x4(q4[3].x, q4[3].y, q4[3].z, q4[3].w);
        *reinterpret_cast<uint4*>(&tile[buf][tid >> 3][(tid & 7) * 16]) = o;
    };

    // ---- A fragments: fp32 V -> e4m3 regs, pre-scaled by CEXP ----
    const int nch = (QG - slot + SLOTS - 1) / SLOTS;   // 6 or 7
    ld_chunk(slot);                                    // overlap LDG with A prologue

    uint32_t a[2][4][4];
    {
        const float* Ab = V + (size_t)(w * 32) * F;
#pragma unroll
        for (int m = 0; m < 2; m++)
#pragma unroll
            for (int kb = 0; kb < 4; kb++) {
                int r0 = m * 16 + g, r1 = r0 + 8;
                int kc = kb * 32 + tg * 4;
                float4 v;
                v = *(const float4*)(Ab + r0 * F + kc);
                a[m][kb][0] = pack_e4m3x4(v.x * CEXP, v.y * CEXP, v.z * CEXP, v.w * CEXP);
                v = *(const float4*)(Ab + r1 * F + kc);
                a[m][kb][1] = pack_e4m3x4(v.x * CEXP, v.y * CEXP, v.z * CEXP, v.w * CEXP);
                v = *(const float4*)(Ab + r0 * F + kc + 16);
                a[m][kb][2] = pack_e4m3x4(v.x * CEXP, v.y * CEXP, v.z * CEXP, v.w * CEXP);
                v = *(const float4*)(Ab + r1 * F + kc + 16);
                a[m][kb][3] = pack_e4m3x4(v.x * CEXP, v.y * CEXP, v.z * CEXP, v.w * CEXP);
            }
    }

    store_chunk(0);
    __syncthreads();
    if (nch > 1) ld_chunk(slot + SLOTS);

    float s00 = 0.f, s01 = 0.f, s10 = 0.f, s11 = 0.f;

    int qg = slot;
#pragma unroll 1
    for (int c = 0; c < nch; c++, qg += SLOTS) {
        const uint32_t bufb = tb + (c & 1) * (TN * SSTR);
        const uint32_t lbase = bufb + (lane & 7) * SSTR + (lane >> 3) * 16;

        float u[8];
#pragma unroll
        for (int n8 = 0; n8 < 8; n8++) {
            uint32_t b0q[4], b1q[4];
            const uint32_t nb = lbase + n8 * 8 * SSTR;
            ldsm_x4(b0q, nb);          // k bytes 0..63  (kb0, kb1)
            ldsm_x4(b1q, nb + 64);     // k bytes 64..127 (kb2, kb3)

            float x0[4] = {0,0,0,0}, x1[4] = {0,0,0,0};
            float y0[4] = {0,0,0,0}, y1[4] = {0,0,0,0};
            mma_fp8(x0, a[0][0], b0q[0], b0q[1]);
            mma_fp8(x1, a[0][2], b1q[0], b1q[1]);
            mma_fp8(y0, a[1][0], b0q[0], b0q[1]);
            mma_fp8(y1, a[1][2], b1q[0], b1q[1]);
            mma_fp8(x0, a[0][1], b0q[2], b0q[3]);
            mma_fp8(x1, a[0][3], b1q[2], b1q[3]);
            mma_fp8(y0, a[1][1], b0q[2], b0q[3]);
            mma_fp8(y1, a[1][3], b1q[2], b1q[3]);

            if (n8 > 0) {   // deferred ex2 of previous iteration (overlaps this iter's mma)
                s00 += ex2f(u[0]) + ex2f(u[1]);
                s01 += ex2f(u[2]) + ex2f(u[3]);
                s10 += ex2f(u[4]) + ex2f(u[5]);
                s11 += ex2f(u[6]) + ex2f(u[7]);
            }
#pragma unroll
            for (int i = 0; i < 4; i++) { u[i] = x0[i] + x1[i]; u[4 + i] = y0[i] + y1[i]; }
        }
        // flush last iteration's exps
        s00 += ex2f(u[0]) + ex2f(u[1]);
        s01 += ex2f(u[2]) + ex2f(u[3]);
        s10 += ex2f(u[4]) + ex2f(u[5]);
        s11 += ex2f(u[6]) + ex2f(u[7]);

        if (c + 1 < nch) store_chunk((c + 1) & 1);   // buf last read in chunk c-1 (pre-barrier)
        __syncthreads();                              // tile (c+1) visible; buf c free for c+2
        if (c + 2 < nch) ld_chunk(qg + 2 * SLOTS);   // full next chunk to hide LDG latency
    }

    // ---- quad reduce over tg, transposed deterministic store ----
    s00 += __shfl_xor_sync(0xFFFFFFFFu, s00, 1); s00 += __shfl_xor_sync(0xFFFFFFFFu, s00, 2);
    s01 += __shfl_xor_sync(0xFFFFFFFFu, s01, 1); s01 += __shfl_xor_sync(0xFFFFFFFFu, s01, 2);
    s10 += __shfl_xor_sync(0xFFFFFFFFu, s10, 1); s10 += __shfl_xor_sync(0xFFFFFFFFu, s10, 2);
    s11 += __shfl_xor_sync(0xFFFFFFFFu, s11, 1); s11 += __shfl_xor_sync(0xFFFFFFFFu, s11, 2);
    if (tg == 0) {
        int rb = w * 32;
        g_sq[(size_t)(rb + g)      * SLOTS + slot] = s00;
        g_sq[(size_t)(rb + g + 8)  * SLOTS + slot] = s01;
        g_sq[(size_t)(rb + g + 16) * SLOTS + slot] = s10;
        g_sq[(size_t)(rb + g + 24) * SLOTS + slot] = s11;
    }
}

// ================= kernel 2: per-row pos + slot reduction (64 CTAs, warp/row) =================
__global__ void __launch_bounds__(256) reduce_kernel(const float* __restrict__ V,
                                                     const float* __restrict__ L) {
    const int w    = threadIdx.x >> 5;
    const int lane = threadIdx.x & 31;
    const int row  = blockIdx.x * 8 + w;      // 64 CTAs x 8 warps = 512 rows

    float4 av = ((const float4*)(V + (size_t)row * F))[lane];
    float4 lv = ((const float4*)(L + (size_t)(row & (B - 1)) * F))[lane];
    float p = av.x * lv.x + av.y * lv.y + av.z * lv.z + av.w * lv.w;
#pragma unroll
    for (int o = 16; o > 0; o >>= 1) p += __shfl_xor_sync(0xFFFFFFFFu, p, o);

    const float* sr = g_sq + (size_t)row * SLOTS;
    float sq = 0.f;
#pragma unroll
    for (int i = lane; i < SLOTS; i += 32) sq += sr[i];
#pragma unroll
    for (int o = 16; o > 0; o >>= 1) sq += __shfl_xor_sync(0xFFFFFFFFu, sq, o);

    if (lane == 0) {
        g_pos[row]   = p * INV_T;
        g_sqrow[row] = sq;
    }
}

// ================= kernel 3: final loss (tiny) =================
__global__ void final_kernel(float* __restrict__ out) {
    __shared__ float sh[R];
    int t = threadIdx.x;          // 512
    float pos = g_pos[t];
    float sq  = g_sqrow[t];
    sh[t] = ex2f(pos * LOG2E);
    __syncthreads();
    for (int off = 128; off > 0; off >>= 1) {
        if ((t & 255) < off) sh[t] += sh[t + off];
        __syncthreads();
    }
    float spos = sh[(t >> 8) << 8];
    __syncthreads();
    sh[t] = pos - logf(spos + sq);
    __syncthreads();
    for (int off = 256; off > 0; off >>= 1) {
        if (t < off) sh[t] += sh[t + off];
        __syncthreads();
    }
    if (t == 0) out[0] = -sh[0] / (float)B;
}

// ================= launch =================
extern "C" void kernel_launch(void* const* d_in, const int* in_sizes, int n_in,
                              void* d_out, int out_size) {
    (void)in_sizes; (void)n_in; (void)out_size;
    const float* V     = (const float*)d_in[0];
    const float* L     = (const float*)d_in[1];
    const float* queue = (const float*)d_in[2];
    float* out = (float*)d_out;

    gemm_exp_kernel<<<SLOTS, 512>>>(V, queue);
    reduce_kernel<<<64, 256>>>(V, L);
    final_kernel<<<1, 512>>>(out);
}

// round 8
// speedup vs baseline: 1.1012x; 1.1012x over previous
#include <cuda_runtime.h>
#include <cuda_bf16.h>
#include <cstdint>

#define DEVINL __device__ __forceinline__

// ---------------- problem constants ----------------
constexpr int F  = 128;      // feature dim (K)
constexpr int B  = 256;      // batch
constexpr int R  = 512;      // J*B GEMM rows
constexpr int Q  = 65536;    // queue size
constexpr int TN = 64;       // queue rows per chunk
constexpr int QG = Q / TN;   // 1024 chunks
constexpr int SLOTS = 148;   // persistent CTAs (1 per SM)
constexpr int SSTR = 272;    // padded bf16 row stride in smem bytes (256 data + 16 pad)
constexpr int NT  = 1024;    // threads per CTA (32 warps, warp = one m16 block)
constexpr float INV_T = 10.0f;
constexpr float LOG2E = 1.4426950408889634f;
constexpr float CEXP  = INV_T * LOG2E;   // exp(10*d) = 2^(CEXP*d); folded into A

constexpr int F32_BUF  = TN * F * 4;     // 32768 raw fp32 chunk
constexpr int BF_BUF   = TN * SSTR;      // 17408 padded bf16 tile
constexpr int SMEM_BYTES = 2 * F32_BUF + 2 * BF_BUF;   // 100352

// ---------------- scratch (no allocs allowed) ----------------
__device__ float g_sq[R * SLOTS];        // [row][slot] partials
__device__ float g_pos[R];
__device__ float g_sqrow[R];

// ---------------- helpers ----------------
DEVINL float ex2f(float x) { float y; asm("ex2.approx.ftz.f32 %0, %1;" : "=f"(y) : "f"(x)); return y; }

DEVINL uint32_t cvt2(float a, float b) {
    __nv_bfloat162 h = __floats2bfloat162_rn(a, b);
    return *reinterpret_cast<uint32_t*>(&h);
}

DEVINL uint32_t smem_u32(const void* p) {
    uint32_t a;
    asm("{ .reg .u64 t; cvta.to.shared.u64 t, %1; cvt.u32.u64 %0, t; }" : "=r"(a) : "l"(p));
    return a;
}

DEVINL void mma16816(float* d, const uint32_t* a, uint32_t b0, uint32_t b1) {
    asm volatile(
        "mma.sync.aligned.m16n8k16.row.col.f32.bf16.bf16.f32 "
        "{%0,%1,%2,%3}, {%4,%5,%6,%7}, {%8,%9}, {%0,%1,%2,%3};"
        : "+f"(d[0]), "+f"(d[1]), "+f"(d[2]), "+f"(d[3])
        : "r"(a[0]), "r"(a[1]), "r"(a[2]), "r"(a[3]), "r"(b0), "r"(b1));
}

DEVINL void ldsm_x4(uint32_t* r, uint32_t addr) {
    asm volatile("ldmatrix.sync.aligned.m8n8.x4.shared.b16 {%0,%1,%2,%3}, [%4];"
                 : "=r"(r[0]), "=r"(r[1]), "=r"(r[2]), "=r"(r[3]) : "r"(addr));
}

DEVINL void cp16(uint32_t smem_dst, const void* gsrc) {
    asm volatile("cp.async.cg.shared.global [%0], [%1], 16;" :: "r"(smem_dst), "l"(gsrc));
}
DEVINL void cp_commit() { asm volatile("cp.async.commit_group;" ::: "memory"); }
DEVINL void cp_wait1()  { asm volatile("cp.async.wait_group 1;" ::: "memory"); }

// ================= kernel 1: persistent HMMA GEMM, fused cvt + exp row-sum =================
// grid = SLOTS. CTA slot: all 512 rows x chunks qg = slot, slot+SLOTS, ...
// 32 warps; warp w owns rows [w*16, w*16+16).
__global__ void __launch_bounds__(NT, 1)
gemm_exp_kernel(const float* __restrict__ V, const float* __restrict__ queue) {
    extern __shared__ char smem[];
    const uint32_t sb   = smem_u32(smem);
    const uint32_t bf_b = sb + 2 * F32_BUF;

    const int tid  = threadIdx.x;                // 0..1023
    const int w    = tid >> 5;                   // 0..31 -> rows w*16..+15
    const int lane = tid & 31;
    const int g    = lane >> 2;
    const int tg   = lane & 3;
    const int slot = blockIdx.x;                 // 0..147

    // ---- A fragments: fp32 V -> bf16 regs, pre-scaled by CEXP (32 regs) ----
    uint32_t a[8][4];
    {
        const float* Ab = V + (size_t)(w * 16) * F;
#pragma unroll
        for (int k = 0; k < 8; k++) {
            int r0 = g, r1 = g + 8;
            int c0 = k * 16 + 2 * tg, c1 = c0 + 8;
            float2 f;
            f = *(const float2*)(Ab + r0 * F + c0); a[k][0] = cvt2(f.x * CEXP, f.y * CEXP);
            f = *(const float2*)(Ab + r1 * F + c0); a[k][1] = cvt2(f.x * CEXP, f.y * CEXP);
            f = *(const float2*)(Ab + r0 * F + c1); a[k][2] = cvt2(f.x * CEXP, f.y * CEXP);
            f = *(const float2*)(Ab + r1 * F + c1); a[k][3] = cvt2(f.x * CEXP, f.y * CEXP);
        }
    }

    // fp32 staging: 64 rows x 512B; each thread 2 x 16B (16 thr/row)
    const int srow = tid >> 4;               // 0..63
    const int sseg = (tid & 15) * 32;        // 32B per thread
    auto stage = [&](int buf, int qg) {
        const char* src = (const char*)(queue + (size_t)qg * TN * F) + srow * 512 + sseg;
        uint32_t dst = sb + buf * F32_BUF + srow * 512 + sseg;
        cp16(dst, src);
        cp16(dst + 16, src + 16);
    };

    // convert: fp32 buf -> padded bf16 tile; thread handles 2 float4 (16B bf16 out)
    auto convert = [&](int buf) {
#pragma unroll
        for (int h = 0; h < 2; h++) {
            int idx = h * NT + tid;          // 0..2047
            int row = idx >> 5, c4 = idx & 31;
            float4 v4 = *((const float4*)(smem + buf * F32_BUF) + idx);
            uint2 o; o.x = cvt2(v4.x, v4.y); o.y = cvt2(v4.z, v4.w);
            *reinterpret_cast<uint2*>(smem + 2 * F32_BUF + buf * BF_BUF + row * SSTR + c4 * 8) = o;
        }
    };

    const int nch = (QG - slot + SLOTS - 1) / SLOTS;   // 6 or 7

    float s0 = 0.f, s1 = 0.f;

    stage(0, slot); cp_commit();
    stage(1, slot + SLOTS); cp_commit();
    cp_wait1();                    // stage(0) done
    convert(0);
    __syncthreads();

    int qg = slot;
#pragma unroll 1
    for (int c = 0; c < nch; c++, qg += SLOTS) {
        if (c + 2 < nch) stage(c & 1, qg + 2 * SLOTS);   // fp32 buf (c+2)&1 == c&1
        cp_commit();                                      // uniform group count

        const uint32_t lbase = bf_b + (c & 1) * BF_BUF + (lane & 7) * SSTR + (lane >> 3) * 16;
        const bool has_next = (c + 1 < nch);

        float u[4];
#pragma unroll
        for (int n8 = 0; n8 < 8; n8++) {
            if (n8 == 4) cp_wait1();                      // stage(c+1) landed
            if (n8 >= 4 && has_next && n8 == 4) convert((c + 1) & 1);

            const uint32_t nb = lbase + n8 * 8 * SSTR;
            float x0[4] = {0,0,0,0}, x1[4] = {0,0,0,0};
#pragma unroll
            for (int kp = 0; kp < 4; kp++) {
                uint32_t bq[4];
                ldsm_x4(bq, nb + kp * 64);
                float* dx = (kp < 2) ? x0 : x1;
                mma16816(dx, a[2 * kp],     bq[0], bq[1]);
                mma16816(dx, a[2 * kp + 1], bq[2], bq[3]);
            }
            if (n8 > 0) {   // deferred ex2 of previous iteration overlaps this iter's mma
                s0 += ex2f(u[0]) + ex2f(u[1]);
                s1 += ex2f(u[2]) + ex2f(u[3]);
            }
#pragma unroll
            for (int i = 0; i < 4; i++) u[i] = x0[i] + x1[i];
        }
        s0 += ex2f(u[0]) + ex2f(u[1]);
        s1 += ex2f(u[2]) + ex2f(u[3]);

        __syncthreads();   // mma(c) done in all warps before convert(c+1)'s tile is read AND
                           // before stage writes land on buf c's fp32 region next iter
    }

    // ---- quad reduce over tg, transposed deterministic store ----
    s0 += __shfl_xor_sync(0xFFFFFFFFu, s0, 1); s0 += __shfl_xor_sync(0xFFFFFFFFu, s0, 2);
    s1 += __shfl_xor_sync(0xFFFFFFFFu, s1, 1); s1 += __shfl_xor_sync(0xFFFFFFFFu, s1, 2);
    if (tg == 0) {
        int rb = w * 16;
        g_sq[(size_t)(rb + g)     * SLOTS + slot] = s0;
        g_sq[(size_t)(rb + g + 8) * SLOTS + slot] = s1;
    }
}

// ================= kernel 2: per-row pos + slot reduction (64 CTAs, warp/row) =================
__global__ void __launch_bounds__(256) reduce_kernel(const float* __restrict__ V,
                                                     const float* __restrict__ L) {
    const int w    = threadIdx.x >> 5;
    const int lane = threadIdx.x & 31;
    const int row  = blockIdx.x * 8 + w;      // 64 CTAs x 8 warps = 512 rows

    float4 av = ((const float4*)(V + (size_t)row * F))[lane];
    float4 lv = ((const float4*)(L + (size_t)(row & (B - 1)) * F))[lane];
    float p = av.x * lv.x + av.y * lv.y + av.z * lv.z + av.w * lv.w;
#pragma unroll
    for (int o = 16; o > 0; o >>= 1) p += __shfl_xor_sync(0xFFFFFFFFu, p, o);

    const float* sr = g_sq + (size_t)row * SLOTS;
    float sq = 0.f;
#pragma unroll
    for (int i = lane; i < SLOTS; i += 32) sq += sr[i];
#pragma unroll
    for (int o = 16; o > 0; o >>= 1) sq += __shfl_xor_sync(0xFFFFFFFFu, sq, o);

    if (lane == 0) {
        g_pos[row]   = p * INV_T;
        g_sqrow[row] = sq;
    }
}

// ================= kernel 3: final loss (tiny) =================
__global__ void final_kernel(float* __restrict__ out) {
    __shared__ float sh[R];
    int t = threadIdx.x;          // 512
    float pos = g_pos[t];
    float sq  = g_sqrow[t];
    sh[t] = ex2f(pos * LOG2E);
    __syncthreads();
    for (int off = 128; off > 0; off >>= 1) {
        if ((t & 255) < off) sh[t] += sh[t + off];
        __syncthreads();
    }
    float spos = sh[(t >> 8) << 8];
    __syncthreads();
    sh[t] = pos - logf(spos + sq);
    __syncthreads();
    for (int off = 256; off > 0; off >>= 1) {
        if (t < off) sh[t] += sh[t + off];
        __syncthreads();
    }
    if (t == 0) out[0] = -sh[0] / (float)B;
}

// ================= launch =================
extern "C" void kernel_launch(void* const* d_in, const int* in_sizes, int n_in,
                              void* d_out, int out_size) {
    (void)in_sizes; (void)n_in; (void)out_size;
    const float* V     = (const float*)d_in[0];
    const float* L     = (const float*)d_in[1];
    const float* queue = (const float*)d_in[2];
    float* out = (float*)d_out;

    cudaFuncSetAttribute(gemm_exp_kernel, cudaFuncAttributeMaxDynamicSharedMemorySize, SMEM_BYTES);

    gemm_exp_kernel<<<SLOTS, NT, SMEM_BYTES>>>(V, queue);
    reduce_kernel<<<64, 256>>>(V, L);
    final_kernel<<<1, 512>>>(out);
}

// round 9
// speedup vs baseline: 1.1087x; 1.0068x over previous
#include <cuda_runtime.h>
#include <cuda_bf16.h>
#include <cstdint>

#define DEVINL __device__ __forceinline__

// ---------------- problem constants ----------------
constexpr int F  = 128;      // feature dim (K)
constexpr int B  = 256;      // batch
constexpr int R  = 512;      // J*B GEMM rows
constexpr int Q  = 65536;    // queue size
constexpr int TN = 64;       // queue rows per chunk
constexpr int QG = Q / TN;   // 1024 chunks
constexpr int SLOTS = 148;   // persistent CTAs (1 per SM)
constexpr int SSTR = 272;    // padded bf16 row stride in smem bytes (256 data + 16 pad)
constexpr int NT  = 1024;    // threads per CTA (32 warps, warp = one m16 block)
constexpr float INV_T = 10.0f;
constexpr float LOG2E = 1.4426950408889634f;
constexpr float CEXP  = INV_T * LOG2E;   // exp(10*d) = 2^(CEXP*d); folded into A

constexpr int BF_BUF = TN * SSTR;        // 17408 per tile buffer

// ---------------- scratch (no allocs allowed) ----------------
__device__ float g_sq[R * SLOTS];        // [row][slot] partials
__device__ float g_pos[R];
__device__ float g_sqrow[R];

// ---------------- helpers ----------------
DEVINL float ex2f(float x) { float y; asm("ex2.approx.ftz.f32 %0, %1;" : "=f"(y) : "f"(x)); return y; }

DEVINL uint32_t cvt2(float a, float b) {
    __nv_bfloat162 h = __floats2bfloat162_rn(a, b);
    return *reinterpret_cast<uint32_t*>(&h);
}

DEVINL uint32_t smem_u32(const void* p) {
    uint32_t a;
    asm("{ .reg .u64 t; cvta.to.shared.u64 t, %1; cvt.u32.u64 %0, t; }" : "=r"(a) : "l"(p));
    return a;
}

DEVINL void mma16816(float* d, const uint32_t* a, uint32_t b0, uint32_t b1) {
    asm volatile(
        "mma.sync.aligned.m16n8k16.row.col.f32.bf16.bf16.f32 "
        "{%0,%1,%2,%3}, {%4,%5,%6,%7}, {%8,%9}, {%0,%1,%2,%3};"
        : "+f"(d[0]), "+f"(d[1]), "+f"(d[2]), "+f"(d[3])
        : "r"(a[0]), "r"(a[1]), "r"(a[2]), "r"(a[3]), "r"(b0), "r"(b1));
}

DEVINL void ldsm_x4(uint32_t* r, uint32_t addr) {
    asm volatile("ldmatrix.sync.aligned.m8n8.x4.shared.b16 {%0,%1,%2,%3}, [%4];"
                 : "=r"(r[0]), "=r"(r[1]), "=r"(r[2]), "=r"(r[3]) : "r"(addr));
}

// ================= kernel 1: persistent HMMA GEMM, direct LDG->cvt->STS pipeline =================
// grid = SLOTS. CTA slot: all 512 rows x chunks qg = slot, slot+SLOTS, ...
// 32 warps; warp w owns rows [w*16, w*16+16).
__global__ void __launch_bounds__(NT, 1)
gemm_exp_kernel(const float* __restrict__ V, const float* __restrict__ queue) {
    __shared__ alignas(16) uint8_t tile[2][TN][SSTR];   // 34816 B
    const uint32_t tb = smem_u32(&tile[0][0][0]);

    const int tid  = threadIdx.x;                // 0..1023
    const int w    = tid >> 5;                   // 0..31 -> rows w*16..+15
    const int lane = tid & 31;
    const int g    = lane >> 2;
    const int tg   = lane & 3;
    const int slot = blockIdx.x;                 // 0..147

    // store 2 float4 (converted) into tile buffer; thread owns elements tid and tid+1024
    auto sts_pair = [&](int buf, const float4& p0, const float4& p1) {
        uint2 o0; o0.x = cvt2(p0.x, p0.y); o0.y = cvt2(p0.z, p0.w);
        uint2 o1; o1.x = cvt2(p1.x, p1.y); o1.y = cvt2(p1.z, p1.w);
        int e0 = tid, e1 = tid + NT;
        *reinterpret_cast<uint2*>(&tile[buf][e0 >> 5][(e0 & 31) * 8]) = o0;
        *reinterpret_cast<uint2*>(&tile[buf][e1 >> 5][(e1 & 31) * 8]) = o1;
    };

    // ---- prologue: start chunk-0 LDG, then build A fragments, then STS ----
    const int nch = (QG - slot + SLOTS - 1) / SLOTS;   // 6 or 7
    float4 p0, p1;
    {
        const float4* qp = (const float4*)queue + (size_t)slot * (TN * F / 4);
        p0 = qp[tid]; p1 = qp[tid + NT];
    }

    // A fragments: fp32 V -> bf16 regs, pre-scaled by CEXP (32 regs)
    uint32_t a[8][4];
    {
        const float* Ab = V + (size_t)(w * 16) * F;
#pragma unroll
        for (int k = 0; k < 8; k++) {
            int c0 = k * 16 + 2 * tg, c1 = c0 + 8;
            float2 f;
            f = *(const float2*)(Ab + g * F + c0);       a[k][0] = cvt2(f.x * CEXP, f.y * CEXP);
            f = *(const float2*)(Ab + (g + 8) * F + c0); a[k][1] = cvt2(f.x * CEXP, f.y * CEXP);
            f = *(const float2*)(Ab + g * F + c1);       a[k][2] = cvt2(f.x * CEXP, f.y * CEXP);
            f = *(const float2*)(Ab + (g + 8) * F + c1); a[k][3] = cvt2(f.x * CEXP, f.y * CEXP);
        }
    }

    sts_pair(0, p0, p1);
    __syncthreads();

    float s0 = 0.f, s1 = 0.f;

    int qg = slot;
#pragma unroll 1
    for (int c = 0; c < nch; c++, qg += SLOTS) {
        const bool pre = (c + 1 < nch);
        const uint32_t lbase = tb + (c & 1) * BF_BUF + (lane & 7) * SSTR + (lane >> 3) * 16;

        float u[4];
#pragma unroll
        for (int i = 0; i < 8; i++) {
            if (i == 0 && pre) {   // prefetch next chunk straight to registers
                const float4* qp = (const float4*)queue + (size_t)(qg + SLOTS) * (TN * F / 4);
                p0 = qp[tid]; p1 = qp[tid + NT];
            }
            if (i == 2 && pre) sts_pair((c + 1) & 1, p0, p1);   // write buffer sealed since barrier c-1

            const int n8 = (i + w) & 7;                 // rotate start per warp: spread LDSM bursts
            const uint32_t nb = lbase + n8 * 8 * SSTR;
            float x0[4] = {0,0,0,0}, x1[4] = {0,0,0,0};
#pragma unroll
            for (int kp = 0; kp < 4; kp++) {
                uint32_t bq[4];
                ldsm_x4(bq, nb + kp * 64);
                float* dx = (kp & 1) ? x1 : x0;         // interleave chains: deps 2 apart
                mma16816(dx, a[2 * kp],     bq[0], bq[1]);
                mma16816(dx, a[2 * kp + 1], bq[2], bq[3]);
            }
            if (i > 0) {   // deferred ex2 of previous iteration overlaps this iter's mma
                s0 += ex2f(u[0]) + ex2f(u[1]);
                s1 += ex2f(u[2]) + ex2f(u[3]);
            }
#pragma unroll
            for (int t = 0; t < 4; t++) u[t] = x0[t] + x1[t];
        }
        s0 += ex2f(u[0]) + ex2f(u[1]);
        s1 += ex2f(u[2]) + ex2f(u[3]);

        __syncthreads();   // all warps done reading buf c; tile (c+1) writes visible
    }

    // ---- quad reduce over tg, transposed deterministic store ----
    s0 += __shfl_xor_sync(0xFFFFFFFFu, s0, 1); s0 += __shfl_xor_sync(0xFFFFFFFFu, s0, 2);
    s1 += __shfl_xor_sync(0xFFFFFFFFu, s1, 1); s1 += __shfl_xor_sync(0xFFFFFFFFu, s1, 2);
    if (tg == 0) {
        int rb = w * 16;
        g_sq[(size_t)(rb + g)     * SLOTS + slot] = s0;
        g_sq[(size_t)(rb + g + 8) * SLOTS + slot] = s1;
    }
}

// ================= kernel 2: per-row pos + slot reduction (64 CTAs, warp/row) =================
__global__ void __launch_bounds__(256) reduce_kernel(const float* __restrict__ V,
                                                     const float* __restrict__ L) {
    const int w    = threadIdx.x >> 5;
    const int lane = threadIdx.x & 31;
    const int row  = blockIdx.x * 8 + w;      // 64 CTAs x 8 warps = 512 rows

    float4 av = ((const float4*)(V + (size_t)row * F))[lane];
    float4 lv = ((const float4*)(L + (size_t)(row & (B - 1)) * F))[lane];
    float p = av.x * lv.x + av.y * lv.y + av.z * lv.z + av.w * lv.w;
#pragma unroll
    for (int o = 16; o > 0; o >>= 1) p += __shfl_xor_sync(0xFFFFFFFFu, p, o);

    const float* sr = g_sq + (size_t)row * SLOTS;
    float sq = 0.f;
#pragma unroll
    for (int i = lane; i < SLOTS; i += 32) sq += sr[i];
#pragma unroll
    for (int o = 16; o > 0; o >>= 1) sq += __shfl_xor_sync(0xFFFFFFFFu, sq, o);

    if (lane == 0) {
        g_pos[row]   = p * INV_T;
        g_sqrow[row] = sq;
    }
}

// ================= kernel 3: final loss (tiny) =================
__global__ void final_kernel(float* __restrict__ out) {
    __shared__ float sh[R];
    int t = threadIdx.x;          // 512
    float pos = g_pos[t];
    float sq  = g_sqrow[t];
    sh[t] = ex2f(pos * LOG2E);
    __syncthreads();
    for (int off = 128; off > 0; off >>= 1) {
        if ((t & 255) < off) sh[t] += sh[t + off];
        __syncthreads();
    }
    float spos = sh[(t >> 8) << 8];
    __syncthreads();
    sh[t] = pos - logf(spos + sq);
    __syncthreads();
    for (int off = 256; off > 0; off >>= 1) {
        if (t < off) sh[t] += sh[t + off];
        __syncthreads();
    }
    if (t == 0) out[0] = -sh[0] / (float)B;
}

// ================= launch =================
extern "C" void kernel_launch(void* const* d_in, const int* in_sizes, int n_in,
                              void* d_out, int out_size) {
    (void)in_sizes; (void)n_in; (void)out_size;
    const float* V     = (const float*)d_in[0];
    const float* L     = (const float*)d_in[1];
    const float* queue = (const float*)d_in[2];
    float* out = (float*)d_out;

    gemm_exp_kernel<<<SLOTS, NT>>>(V, queue);
    reduce_kernel<<<64, 256>>>(V, L);
    final_kernel<<<1, 512>>>(out);
}